// round 1
// baseline (speedup 1.0000x reference)
#include <cuda_runtime.h>

#define S_LEN 128
#define Q_LEN 256
#define KV_LEN 256
#define NH 8
#define DH 32
#define HD 256           // NH*DH
#define ROWS 32768       // S_LEN*Q_LEN (== S_LEN*KV_LEN)

// Scratch (device globals: no allocation allowed in kernel_launch)
__device__ float g_Qp[ROWS * HD];
__device__ float g_Kp[ROWS * HD];
__device__ float g_Vp[ROWS * HD];
__device__ float g_O [ROWS * HD];

// ---------------------------------------------------------------------------
// QKV projection: out[row, c] = sum_k x[row,k] * w[k,c], x:[32768,64], w:[64,256]
// One block = 64 rows x all 256 cols. w fully in SMEM, x tile padded (stride 68).
// Thread microtile: 4 rows x 16 cols (4 float4 groups spaced 64 apart -> coalesced).
// ---------------------------------------------------------------------------
#define PROJ_SMEM ((16384 + 64 * 68) * 4)

__global__ __launch_bounds__(256) void proj_kernel(
    const float* __restrict__ xq, const float* __restrict__ xkv,
    const float* __restrict__ wq, const float* __restrict__ wk,
    const float* __restrict__ wv) {
  extern __shared__ float sm[];
  float* ws = sm;            // [64][256]
  float* xs = sm + 16384;    // [64][68] padded

  const float* x; const float* w; float* out;
  if (blockIdx.y == 0)      { x = xq;  w = wq; out = g_Qp; }
  else if (blockIdx.y == 1) { x = xkv; w = wk; out = g_Kp; }
  else                      { x = xkv; w = wv; out = g_Vp; }

  const int tid = threadIdx.x;
  const int row0 = blockIdx.x * 64;

  // Load weights (64*256 floats, contiguous) and x tile (64*64, contiguous)
  {
    const float4* wg = (const float4*)w;
    float4* ws4 = (float4*)ws;
#pragma unroll
    for (int i = tid; i < 4096; i += 256) ws4[i] = wg[i];
    const float4* xg = (const float4*)(x + (size_t)row0 * 64);
#pragma unroll
    for (int i = tid; i < 1024; i += 256) {
      int r = i >> 4, c4 = i & 15;
      *(float4*)(xs + r * 68 + c4 * 4) = xg[i];
    }
  }
  __syncthreads();

  const int tr = tid >> 4;        // 0..15 -> 4 rows each
  const int tc = tid & 15;        // 0..15 -> cols tc*4 + j4*64
  const int r0 = tr * 4;

  float4 acc[4][4];
#pragma unroll
  for (int i = 0; i < 4; i++)
#pragma unroll
    for (int j = 0; j < 4; j++) acc[i][j] = make_float4(0.f, 0.f, 0.f, 0.f);

#pragma unroll 4
  for (int k = 0; k < 64; k++) {
    float xv[4];
#pragma unroll
    for (int i = 0; i < 4; i++) xv[i] = xs[(r0 + i) * 68 + k];
#pragma unroll
    for (int j4 = 0; j4 < 4; j4++) {
      float4 w4 = *(const float4*)(ws + k * 256 + j4 * 64 + tc * 4);
#pragma unroll
      for (int i = 0; i < 4; i++) {
        acc[i][j4].x += xv[i] * w4.x;
        acc[i][j4].y += xv[i] * w4.y;
        acc[i][j4].z += xv[i] * w4.z;
        acc[i][j4].w += xv[i] * w4.w;
      }
    }
  }

#pragma unroll
  for (int i = 0; i < 4; i++)
#pragma unroll
    for (int j4 = 0; j4 < 4; j4++)
      *(float4*)(out + (size_t)(row0 + r0 + i) * 256 + j4 * 64 + tc * 4) = acc[i][j4];
}

// ---------------------------------------------------------------------------
// Attention: one block per (s, h). 256 threads, one q-row per thread.
// K,V tiles in SMEM; bias staged in 32-wide KV chunks with stride-33 padding.
// Softmax without max-subtraction (scores are O(6); masked -> exp(-1e9)=0).
// ---------------------------------------------------------------------------
#define ATTN_SMEM ((8192 + 8192 + 256 * 33 + 32) * 4)

__global__ __launch_bounds__(256) void attn_kernel(
    const float* __restrict__ mask, const float* __restrict__ bias) {
  extern __shared__ float sm[];
  float* ks = sm;                    // [256][32]
  float* vs = sm + 8192;             // [256][32]
  float* bs = sm + 16384;            // [256][33] padded
  float* ms = sm + 16384 + 8448;     // [32]

  const int tid = threadIdx.x;
  const int s = blockIdx.x;
  const int h = blockIdx.y;

  // Stage K, V tiles (coalesced: 8 consecutive float4 per row)
  {
    const float* Kg = g_Kp + (size_t)s * KV_LEN * HD + h * DH;
    const float* Vg = g_Vp + (size_t)s * KV_LEN * HD + h * DH;
    float4* ks4 = (float4*)ks;
    float4* vs4 = (float4*)vs;
#pragma unroll
    for (int i = tid; i < 2048; i += 256) {
      int kj = i >> 3, d4 = i & 7;
      ks4[i] = *(const float4*)(Kg + kj * HD + d4 * 4);
      vs4[i] = *(const float4*)(Vg + kj * HD + d4 * 4);
    }
  }

  // Per-thread q row, pre-scaled by 1/sqrt(32)
  float4 q4[8];
  {
    const float* Qg = g_Qp + ((size_t)s * Q_LEN + tid) * HD + h * DH;
    const float scaling = 0.17677669529663687f;
#pragma unroll
    for (int d4 = 0; d4 < 8; d4++) {
      float4 t = *(const float4*)(Qg + d4 * 4);
      q4[d4] = make_float4(t.x * scaling, t.y * scaling, t.z * scaling, t.w * scaling);
    }
  }

  float4 o4[8];
#pragma unroll
  for (int d4 = 0; d4 < 8; d4++) o4[d4] = make_float4(0.f, 0.f, 0.f, 0.f);
  float l = 0.f;

  const float* Bh = bias + (size_t)h * Q_LEN * KV_LEN;
  const float4* ks4 = (const float4*)ks;
  const float4* vs4 = (const float4*)vs;

  for (int jc = 0; jc < KV_LEN; jc += 32) {
    __syncthreads();   // covers K/V staging (iter 0) and prior-chunk compute
    // Stage bias chunk [256 q][32 kv] -> bs[qi*33 + j] (conflict-free pattern)
#pragma unroll
    for (int i = tid; i < 2048; i += 256) {
      int qi = i >> 3, j4 = i & 7;
      float4 b = *(const float4*)(Bh + (size_t)qi * KV_LEN + jc + j4 * 4);
      float* dst = bs + qi * 33 + j4 * 4;
      dst[0] = b.x; dst[1] = b.y; dst[2] = b.z; dst[3] = b.w;
    }
    if (tid < 32) ms[tid] = (mask[s * KV_LEN + jc + tid] - 1.0f) * 1.0e9f;
    __syncthreads();

#pragma unroll 2
    for (int j = 0; j < 32; ++j) {
      const int kj = jc + j;
      const float4* kr = ks4 + kj * 8;
      float s0 = 0.f, s1 = 0.f, s2 = 0.f, s3 = 0.f;
#pragma unroll
      for (int d4 = 0; d4 < 8; d4++) {
        float4 kk = kr[d4];
        s0 += q4[d4].x * kk.x;
        s1 += q4[d4].y * kk.y;
        s2 += q4[d4].z * kk.z;
        s3 += q4[d4].w * kk.w;
      }
      float sc = (s0 + s1) + (s2 + s3) + bs[tid * 33 + j] + ms[j];
      float p = __expf(sc);
      l += p;
      const float4* vr = vs4 + kj * 8;
#pragma unroll
      for (int d4 = 0; d4 < 8; d4++) {
        float4 vv = vr[d4];
        o4[d4].x += p * vv.x;
        o4[d4].y += p * vv.y;
        o4[d4].z += p * vv.z;
        o4[d4].w += p * vv.w;
      }
    }
  }

  const float inv = 1.0f / l;
  float* Og = g_O + ((size_t)s * Q_LEN + tid) * HD + h * DH;
#pragma unroll
  for (int d4 = 0; d4 < 8; d4++) {
    *(float4*)(Og + d4 * 4) =
        make_float4(o4[d4].x * inv, o4[d4].y * inv, o4[d4].z * inv, o4[d4].w * inv);
  }
}

// ---------------------------------------------------------------------------
// Output projection: out[row,c] = sum_k O[row,k]*wo[k,c] + bo[c]
// x:[32768,256], wo:[256,64]. Block = 64 rows x 64 cols.
// ---------------------------------------------------------------------------
#define OPROJ_SMEM ((16384 + 64 * 260) * 4)

__global__ __launch_bounds__(256) void oproj_kernel(
    const float* __restrict__ wo, const float* __restrict__ bo,
    float* __restrict__ out) {
  extern __shared__ float sm[];
  float* ws = sm;            // [256][64]
  float* xs = sm + 16384;    // [64][260] padded

  const int tid = threadIdx.x;
  const int row0 = blockIdx.x * 64;

  {
    const float4* wg = (const float4*)wo;
    float4* ws4 = (float4*)ws;
#pragma unroll
    for (int i = tid; i < 4096; i += 256) ws4[i] = wg[i];
    const float4* xg = (const float4*)(g_O + (size_t)row0 * 256);
#pragma unroll
    for (int i = tid; i < 4096; i += 256) {
      int r = i >> 6, c4 = i & 63;
      *(float4*)(xs + r * 260 + c4 * 4) = xg[i];
    }
  }
  __syncthreads();

  const int tr = tid >> 4;   // 4 rows each
  const int tc = tid & 15;   // 4 cols each
  const int r0 = tr * 4;

  float4 acc[4];
#pragma unroll
  for (int i = 0; i < 4; i++) acc[i] = make_float4(0.f, 0.f, 0.f, 0.f);

#pragma unroll 4
  for (int k = 0; k < 256; k++) {
    float4 w4 = *(const float4*)(ws + k * 64 + tc * 4);
#pragma unroll
    for (int i = 0; i < 4; i++) {
      float xv = xs[(r0 + i) * 260 + k];
      acc[i].x += xv * w4.x;
      acc[i].y += xv * w4.y;
      acc[i].z += xv * w4.z;
      acc[i].w += xv * w4.w;
    }
  }

  float4 bb = *(const float4*)(bo + tc * 4);
#pragma unroll
  for (int i = 0; i < 4; i++) {
    float4 r = make_float4(acc[i].x + bb.x, acc[i].y + bb.y,
                           acc[i].z + bb.z, acc[i].w + bb.w);
    *(float4*)(out + (size_t)(row0 + r0 + i) * 64 + tc * 4) = r;
  }
}

// ---------------------------------------------------------------------------
extern "C" void kernel_launch(void* const* d_in, const int* in_sizes, int n_in,
                              void* d_out, int out_size) {
  const float* input_q  = (const float*)d_in[0];
  const float* input_kv = (const float*)d_in[1];
  const float* mask     = (const float*)d_in[2];
  const float* bias     = (const float*)d_in[3];
  const float* wq       = (const float*)d_in[4];
  const float* wk       = (const float*)d_in[5];
  const float* wv       = (const float*)d_in[6];
  const float* wo       = (const float*)d_in[7];
  const float* bo       = (const float*)d_in[8];
  float* out = (float*)d_out;

  cudaFuncSetAttribute(proj_kernel,  cudaFuncAttributeMaxDynamicSharedMemorySize, PROJ_SMEM);
  cudaFuncSetAttribute(attn_kernel,  cudaFuncAttributeMaxDynamicSharedMemorySize, ATTN_SMEM);
  cudaFuncSetAttribute(oproj_kernel, cudaFuncAttributeMaxDynamicSharedMemorySize, OPROJ_SMEM);

  proj_kernel<<<dim3(ROWS / 64, 3), 256, PROJ_SMEM>>>(input_q, input_kv, wq, wk, wv);
  attn_kernel<<<dim3(S_LEN, NH), 256, ATTN_SMEM>>>(mask, bias);
  oproj_kernel<<<ROWS / 64, 256, OPROJ_SMEM>>>(wo, bo, out);
}

// round 3
// speedup vs baseline: 2.4634x; 2.4634x over previous
#include <cuda_runtime.h>

#define S_LEN 128
#define Q_LEN 256
#define KV_LEN 256
#define NH 8
#define DH 32
#define HD 256           // NH*DH
#define ROWS 32768       // S_LEN*Q_LEN

// Scratch (device globals: no allocation allowed)
__device__ float g_Qp[ROWS * HD];
__device__ float g_Kp[ROWS * HD];
__device__ float g_Vp[ROWS * HD];
__device__ float g_O [ROWS * HD];

// Round fp32 -> tf32 (round-to-nearest), kept in a 32-bit float container.
__device__ __forceinline__ float f2tf(float x) {
  unsigned r;
  asm("cvt.rna.tf32.f32 %0, %1;" : "=r"(r) : "f"(x));
  return __uint_as_float(r);
}

// D += A(16x8) * B(8x8), tf32 inputs (bit-passed), fp32 accum.
__device__ __forceinline__ void mma8(float4& c, float a0, float a1, float a2,
                                     float a3, float b0, float b1) {
  asm volatile(
      "mma.sync.aligned.m16n8k8.row.col.f32.tf32.tf32.f32 "
      "{%0,%1,%2,%3}, {%4,%5,%6,%7}, {%8,%9}, {%0,%1,%2,%3};"
      : "+f"(c.x), "+f"(c.y), "+f"(c.z), "+f"(c.w)
      : "r"(__float_as_uint(a0)), "r"(__float_as_uint(a1)),
        "r"(__float_as_uint(a2)), "r"(__float_as_uint(a3)),
        "r"(__float_as_uint(b0)), "r"(__float_as_uint(b1)));
}

// ---------------------------------------------------------------------------
// QKV projection: X[32768,64] @ W[64,256]. Block = 64 rows x 128 cols (y = col
// half, z = which matrix). 8 warps: warp tile 16 rows x 64 cols.
// ---------------------------------------------------------------------------
#define PROJ_SMEM ((64 * 68 + 64 * 132) * 4)

__global__ __launch_bounds__(256, 3) void proj_kernel(
    const float* __restrict__ xq, const float* __restrict__ xkv,
    const float* __restrict__ wq, const float* __restrict__ wk,
    const float* __restrict__ wv) {
  extern __shared__ float sm[];
  float* Xs = sm;              // [64][68]
  float* Ws = sm + 64 * 68;    // [64][132]

  const float* x; const float* w; float* out;
  if (blockIdx.z == 0)      { x = xq;  w = wq; out = g_Qp; }
  else if (blockIdx.z == 1) { x = xkv; w = wk; out = g_Kp; }
  else                      { x = xkv; w = wv; out = g_Vp; }

  const int tid = threadIdx.x;
  const int row0 = blockIdx.x * 64;
  const int nh = blockIdx.y * 128;

  // Stage W half [64][128] and X tile [64][64], rounded to tf32
#pragma unroll
  for (int i = tid; i < 2048; i += 256) {
    int k = i >> 5, c4 = i & 31;
    float4 v = *(const float4*)(w + k * 256 + nh + c4 * 4);
    float* d = Ws + k * 132 + c4 * 4;
    d[0] = f2tf(v.x); d[1] = f2tf(v.y); d[2] = f2tf(v.z); d[3] = f2tf(v.w);
  }
#pragma unroll
  for (int i = tid; i < 1024; i += 256) {
    int r = i >> 4, c4 = i & 15;
    float4 v = *(const float4*)(x + (size_t)(row0 + r) * 64 + c4 * 4);
    float* d = Xs + r * 68 + c4 * 4;
    d[0] = f2tf(v.x); d[1] = f2tf(v.y); d[2] = f2tf(v.z); d[3] = f2tf(v.w);
  }
  __syncthreads();

  const int wid = tid >> 5, lane = tid & 31;
  const int r4 = lane >> 2, c4 = lane & 3;
  const int wr = (wid >> 1) * 16;
  const int wc = (wid & 1) * 64;

  float4 acc[8];
#pragma unroll
  for (int i = 0; i < 8; i++) acc[i] = make_float4(0.f, 0.f, 0.f, 0.f);

#pragma unroll
  for (int kk = 0; kk < 8; kk++) {
    const int k0 = kk * 8;
    float a0 = Xs[(wr + r4) * 68 + k0 + c4];
    float a1 = Xs[(wr + r4 + 8) * 68 + k0 + c4];
    float a2 = Xs[(wr + r4) * 68 + k0 + c4 + 4];
    float a3 = Xs[(wr + r4 + 8) * 68 + k0 + c4 + 4];
#pragma unroll
    for (int nf = 0; nf < 8; nf++) {
      float b0 = Ws[(k0 + c4) * 132 + wc + nf * 8 + r4];
      float b1 = Ws[(k0 + c4 + 4) * 132 + wc + nf * 8 + r4];
      mma8(acc[nf], a0, a1, a2, a3, b0, b1);
    }
  }

#pragma unroll
  for (int nf = 0; nf < 8; nf++) {
    int col = nh + wc + nf * 8 + 2 * c4;
    int row = row0 + wr + r4;
    *(float2*)(out + (size_t)row * 256 + col) = make_float2(acc[nf].x, acc[nf].y);
    *(float2*)(out + (size_t)(row + 8) * 256 + col) = make_float2(acc[nf].z, acc[nf].w);
  }
}

// ---------------------------------------------------------------------------
// Fused attention, one block per (s,h). 8 warps, warp = 32 q rows (2 m-tiles).
// S = QK^T via mma, softmax in regs, P->A fragment conversion via shuffles,
// O = P*V via mma. Bias read directly from global in C-frag layout.
// ---------------------------------------------------------------------------
#define ATTN_SMEM ((3 * 256 * 36 + 256) * 4)

__global__ __launch_bounds__(256, 2) void attn_kernel(
    const float* __restrict__ mask, const float* __restrict__ bias) {
  extern __shared__ float sm[];
  float* Qs = sm;                  // [256][36]
  float* Ks = sm + 9216;           // [256][36]
  float* Vs = sm + 18432;          // [256][36]
  float* ms = sm + 27648;          // [256]

  const int tid = threadIdx.x;
  const int s = blockIdx.x;
  const int h = blockIdx.y;

  const float scaling = 0.17677669529663687f;  // 1/sqrt(32)
  {
    const float* Qg = g_Qp + (size_t)s * Q_LEN * HD + h * DH;
    const float* Kg = g_Kp + (size_t)s * KV_LEN * HD + h * DH;
    const float* Vg = g_Vp + (size_t)s * KV_LEN * HD + h * DH;
#pragma unroll
    for (int i = tid; i < 2048; i += 256) {
      int r = i >> 3, d4 = i & 7;
      float4 q = *(const float4*)(Qg + (size_t)r * HD + d4 * 4);
      float4 k = *(const float4*)(Kg + (size_t)r * HD + d4 * 4);
      float4 v = *(const float4*)(Vg + (size_t)r * HD + d4 * 4);
      float* qd = Qs + r * 36 + d4 * 4;
      qd[0] = f2tf(q.x * scaling); qd[1] = f2tf(q.y * scaling);
      qd[2] = f2tf(q.z * scaling); qd[3] = f2tf(q.w * scaling);
      float* kd = Ks + r * 36 + d4 * 4;
      kd[0] = f2tf(k.x); kd[1] = f2tf(k.y); kd[2] = f2tf(k.z); kd[3] = f2tf(k.w);
      float* vd = Vs + r * 36 + d4 * 4;
      vd[0] = f2tf(v.x); vd[1] = f2tf(v.y); vd[2] = f2tf(v.z); vd[3] = f2tf(v.w);
    }
    ms[tid] = (mask[s * KV_LEN + tid] - 1.0f) * 1.0e9f;
  }
  __syncthreads();

  const int w = tid >> 5, lane = tid & 31;
  const int r4 = lane >> 2, c4 = lane & 3;
  const int qb[2] = {w * 32, w * 32 + 16};

  float4 o[2][4];
#pragma unroll
  for (int mt = 0; mt < 2; mt++)
#pragma unroll
    for (int nf = 0; nf < 4; nf++) o[mt][nf] = make_float4(0.f, 0.f, 0.f, 0.f);
  float2 lp[2] = {make_float2(0.f, 0.f), make_float2(0.f, 0.f)};

  // bias base pointers (per m-tile, rows r4 and r4+8), C-frag col = 2*c4
  const float* Bh = bias + (size_t)h * Q_LEN * KV_LEN;
  const float* bb0[2]; const float* bb1[2];
#pragma unroll
  for (int mt = 0; mt < 2; mt++) {
    bb0[mt] = Bh + (size_t)(qb[mt] + r4) * KV_LEN + 2 * c4;
    bb1[mt] = Bh + (size_t)(qb[mt] + r4 + 8) * KV_LEN + 2 * c4;
  }
  float2 bp[2][2];
#pragma unroll
  for (int mt = 0; mt < 2; mt++) {
    bp[mt][0] = *(const float2*)(bb0[mt]);
    bp[mt][1] = *(const float2*)(bb1[mt]);
  }

  const int src0 = (lane & ~3) | (c4 >> 1);
  const int src2 = src0 + 2;
  const bool odd = (c4 & 1);

#pragma unroll 1
  for (int kv0 = 0; kv0 < KV_LEN; kv0 += 8) {
    // S = Q K^T (per m-tile), fp32 accum
    float4 S[2] = {make_float4(0.f, 0.f, 0.f, 0.f), make_float4(0.f, 0.f, 0.f, 0.f)};
#pragma unroll
    for (int dd = 0; dd < 4; dd++) {
      const int d0 = dd * 8;
      float b0 = Ks[(kv0 + r4) * 36 + d0 + c4];
      float b1 = Ks[(kv0 + r4) * 36 + d0 + c4 + 4];
#pragma unroll
      for (int mt = 0; mt < 2; mt++) {
        float a0 = Qs[(qb[mt] + r4) * 36 + d0 + c4];
        float a1 = Qs[(qb[mt] + r4 + 8) * 36 + d0 + c4];
        float a2 = Qs[(qb[mt] + r4) * 36 + d0 + c4 + 4];
        float a3 = Qs[(qb[mt] + r4 + 8) * 36 + d0 + c4 + 4];
        mma8(S[mt], a0, a1, a2, a3, b0, b1);
      }
    }

    // V fragments for this kv chunk (shared across m-tiles)
    float vb0[4], vb1[4];
#pragma unroll
    for (int nf = 0; nf < 4; nf++) {
      vb0[nf] = Vs[(kv0 + c4) * 36 + nf * 8 + r4];
      vb1[nf] = Vs[(kv0 + 4 + c4) * 36 + nf * 8 + r4];
    }

    float m0 = ms[kv0 + 2 * c4];
    float m1 = ms[kv0 + 2 * c4 + 1];

    // prefetch next chunk's bias
    float2 nb[2][2];
    if (kv0 < KV_LEN - 8) {
#pragma unroll
      for (int mt = 0; mt < 2; mt++) {
        nb[mt][0] = *(const float2*)(bb0[mt] + kv0 + 8);
        nb[mt][1] = *(const float2*)(bb1[mt] + kv0 + 8);
      }
    }

#pragma unroll
    for (int mt = 0; mt < 2; mt++) {
      float p0 = __expf(S[mt].x + bp[mt][0].x + m0);
      float p1 = __expf(S[mt].y + bp[mt][0].y + m1);
      float p2 = __expf(S[mt].z + bp[mt][1].x + m0);
      float p3 = __expf(S[mt].w + bp[mt][1].y + m1);
      lp[mt].x += p0 + p1;
      lp[mt].y += p2 + p3;

      // C-layout -> A-layout via shuffles
      float t00 = __shfl_sync(0xffffffffu, p0, src0);
      float t01 = __shfl_sync(0xffffffffu, p1, src0);
      float t20 = __shfl_sync(0xffffffffu, p2, src0);
      float t21 = __shfl_sync(0xffffffffu, p3, src0);
      float u00 = __shfl_sync(0xffffffffu, p0, src2);
      float u01 = __shfl_sync(0xffffffffu, p1, src2);
      float u20 = __shfl_sync(0xffffffffu, p2, src2);
      float u21 = __shfl_sync(0xffffffffu, p3, src2);
      float a0 = odd ? t01 : t00;
      float a1 = odd ? t21 : t20;
      float a2 = odd ? u01 : u00;
      float a3 = odd ? u21 : u20;

#pragma unroll
      for (int nf = 0; nf < 4; nf++)
        mma8(o[mt][nf], a0, a1, a2, a3, vb0[nf], vb1[nf]);
    }

    if (kv0 < KV_LEN - 8) {
#pragma unroll
      for (int mt = 0; mt < 2; mt++) { bp[mt][0] = nb[mt][0]; bp[mt][1] = nb[mt][1]; }
    }
  }

  // finalize: row sums across the 4-lane quad, normalize, store
#pragma unroll
  for (int mt = 0; mt < 2; mt++) {
    lp[mt].x += __shfl_xor_sync(0xffffffffu, lp[mt].x, 1);
    lp[mt].x += __shfl_xor_sync(0xffffffffu, lp[mt].x, 2);
    lp[mt].y += __shfl_xor_sync(0xffffffffu, lp[mt].y, 1);
    lp[mt].y += __shfl_xor_sync(0xffffffffu, lp[mt].y, 2);
    float inv0 = 1.0f / lp[mt].x;
    float inv8 = 1.0f / lp[mt].y;
    float* base = g_O + ((size_t)s * Q_LEN + qb[mt] + r4) * HD + h * DH;
#pragma unroll
    for (int nf = 0; nf < 4; nf++) {
      int col = nf * 8 + 2 * c4;
      *(float2*)(base + col) = make_float2(o[mt][nf].x * inv0, o[mt][nf].y * inv0);
      *(float2*)(base + 8 * HD + col) =
          make_float2(o[mt][nf].z * inv8, o[mt][nf].w * inv8);
    }
  }
}

// ---------------------------------------------------------------------------
// Output projection: g_O[32768,256] @ wo[256,64] + bo. Block = 128 rows x 64
// cols, 8 warps stacked over rows, K chunked by 64.
// ---------------------------------------------------------------------------
#define OPROJ_SMEM ((256 * 68 + 128 * 68) * 4)

__global__ __launch_bounds__(256, 2) void oproj_kernel(
    const float* __restrict__ wo, const float* __restrict__ bo,
    float* __restrict__ out) {
  extern __shared__ float sm[];
  float* Ws = sm;               // [256][68]
  float* Xs = sm + 256 * 68;    // [128][68]

  const int tid = threadIdx.x;
  const int row0 = blockIdx.x * 128;

#pragma unroll
  for (int i = tid; i < 4096; i += 256) {
    int k = i >> 4, c4 = i & 15;
    float4 v = *(const float4*)(wo + (size_t)k * 64 + c4 * 4);
    float* d = Ws + k * 68 + c4 * 4;
    d[0] = f2tf(v.x); d[1] = f2tf(v.y); d[2] = f2tf(v.z); d[3] = f2tf(v.w);
  }

  const int wid = tid >> 5, lane = tid & 31;
  const int r4 = lane >> 2, c4 = lane & 3;
  const int wr = wid * 16;

  float4 acc[8];
#pragma unroll
  for (int i = 0; i < 8; i++) acc[i] = make_float4(0.f, 0.f, 0.f, 0.f);

#pragma unroll 1
  for (int kc = 0; kc < 4; kc++) {
    __syncthreads();  // previous chunk's mma reads done (and Ws ready on kc=0)
#pragma unroll
    for (int i = tid; i < 2048; i += 256) {
      int r = i >> 4, cc = i & 15;
      float4 v = *(const float4*)(g_O + (size_t)(row0 + r) * 256 + kc * 64 + cc * 4);
      float* d = Xs + r * 68 + cc * 4;
      d[0] = f2tf(v.x); d[1] = f2tf(v.y); d[2] = f2tf(v.z); d[3] = f2tf(v.w);
    }
    __syncthreads();

#pragma unroll
    for (int kk = 0; kk < 8; kk++) {
      const int k0 = kk * 8;
      float a0 = Xs[(wr + r4) * 68 + k0 + c4];
      float a1 = Xs[(wr + r4 + 8) * 68 + k0 + c4];
      float a2 = Xs[(wr + r4) * 68 + k0 + c4 + 4];
      float a3 = Xs[(wr + r4 + 8) * 68 + k0 + c4 + 4];
#pragma unroll
      for (int nf = 0; nf < 8; nf++) {
        float b0 = Ws[(kc * 64 + k0 + c4) * 68 + nf * 8 + r4];
        float b1 = Ws[(kc * 64 + k0 + c4 + 4) * 68 + nf * 8 + r4];
        mma8(acc[nf], a0, a1, a2, a3, b0, b1);
      }
    }
  }

#pragma unroll
  for (int nf = 0; nf < 8; nf++) {
    int col = nf * 8 + 2 * c4;
    float2 bb = *(const float2*)(bo + col);  // cols col, col+1 (same for both rows)
    int row = row0 + wr + r4;
    *(float2*)(out + (size_t)row * 64 + col) =
        make_float2(acc[nf].x + bb.x, acc[nf].y + bb.y);
    *(float2*)(out + (size_t)(row + 8) * 64 + col) =
        make_float2(acc[nf].z + bb.x, acc[nf].w + bb.y);
  }
}

// ---------------------------------------------------------------------------
extern "C" void kernel_launch(void* const* d_in, const int* in_sizes, int n_in,
                              void* d_out, int out_size) {
  const float* input_q  = (const float*)d_in[0];
  const float* input_kv = (const float*)d_in[1];
  const float* mask     = (const float*)d_in[2];
  const float* bias     = (const float*)d_in[3];
  const float* wq       = (const float*)d_in[4];
  const float* wk       = (const float*)d_in[5];
  const float* wv       = (const float*)d_in[6];
  const float* wo       = (const float*)d_in[7];
  const float* bo       = (const float*)d_in[8];
  float* out = (float*)d_out;

  cudaFuncSetAttribute(proj_kernel,  cudaFuncAttributeMaxDynamicSharedMemorySize, PROJ_SMEM);
  cudaFuncSetAttribute(attn_kernel,  cudaFuncAttributeMaxDynamicSharedMemorySize, ATTN_SMEM);
  cudaFuncSetAttribute(oproj_kernel, cudaFuncAttributeMaxDynamicSharedMemorySize, OPROJ_SMEM);

  proj_kernel<<<dim3(ROWS / 64, 2, 3), 256, PROJ_SMEM>>>(input_q, input_kv, wq, wk, wv);
  attn_kernel<<<dim3(S_LEN, NH), 256, ATTN_SMEM>>>(mask, bias);
  oproj_kernel<<<ROWS / 128, 256, OPROJ_SMEM>>>(wo, bo, out);
}

// round 4
// speedup vs baseline: 2.5725x; 1.0443x over previous
#include <cuda_runtime.h>

#define S_LEN 128
#define Q_LEN 256
#define KV_LEN 256
#define NH 8
#define DH 32
#define HD 256
#define ROWS 32768

// Scratch (device globals)
__device__ float g_Wf[3 * 16384];   // proj W frags  [z][kk8][nfg32][lane32][2]
__device__ float g_Wof[16384];      // oproj W frags [kk32][nfg8][lane32][2]
__device__ float g_Qf[ROWS * HD];   // [s][h][qt16][dd4][lane32][4]
__device__ float g_Kf[ROWS * HD];   // [s][h][kt32][dd4][lane32][2]
__device__ float g_Vf[ROWS * HD];   // [s][h][kc32][nf4][lane32][2]
__device__ float g_O [ROWS * HD];   // row-major, tf32-rounded

__device__ __forceinline__ float f2tf(float x) {
  unsigned r;
  asm("cvt.rna.tf32.f32 %0, %1;" : "=r"(r) : "f"(x));
  return __uint_as_float(r);
}

__device__ __forceinline__ void mma8(float4& c, float a0, float a1, float a2,
                                     float a3, float b0, float b1) {
  asm volatile(
      "mma.sync.aligned.m16n8k8.row.col.f32.tf32.tf32.f32 "
      "{%0,%1,%2,%3}, {%4,%5,%6,%7}, {%8,%9}, {%0,%1,%2,%3};"
      : "+f"(c.x), "+f"(c.y), "+f"(c.z), "+f"(c.w)
      : "r"(__float_as_uint(a0)), "r"(__float_as_uint(a1)),
        "r"(__float_as_uint(a2)), "r"(__float_as_uint(a3)),
        "r"(__float_as_uint(b0)), "r"(__float_as_uint(b1)));
}

// ---------------------------------------------------------------------------
// Prep: weights -> lane-major B-fragment layouts (tf32-rounded).
// B frag for m16n8k8: thread(r4,c4) holds B[k0+c4][col], B[k0+c4+4][col],
// col = nfg*8 + r4. Pair stored adjacent; lane-major for conflict-free LDS.64.
// ---------------------------------------------------------------------------
__global__ void prep_kernel(const float* __restrict__ wq,
                            const float* __restrict__ wk,
                            const float* __restrict__ wv,
                            const float* __restrict__ wo) {
  const float scale = 0.17677669529663687f;  // 1/sqrt(32), baked into wq
  for (int id = blockIdx.x * 256 + threadIdx.x; id < 65536; id += 64 * 256) {
    if (id < 49152) {
      int z = id >> 14, rem = id & 16383;
      int p = rem & 1, lane = (rem >> 1) & 31, nfg = (rem >> 6) & 31, kk = rem >> 11;
      int r4 = lane >> 2, c4 = lane & 3;
      const float* w = (z == 0) ? wq : (z == 1) ? wk : wv;
      float v = w[(kk * 8 + c4 + 4 * p) * 256 + nfg * 8 + r4];
      if (z == 0) v *= scale;
      g_Wf[id] = f2tf(v);
    } else {
      int id2 = id - 49152;
      int p = id2 & 1, lane = (id2 >> 1) & 31, nfg = (id2 >> 6) & 7, kk = id2 >> 9;
      int r4 = lane >> 2, c4 = lane & 3;
      g_Wof[id2] = f2tf(wo[(kk * 8 + c4 + 4 * p) * 64 + nfg * 8 + r4]);
    }
  }
}

// ---------------------------------------------------------------------------
// QKV projection: X[32768,64] @ Wz[64,256]. Block = 64 rows x 256 cols,
// 8 warps (2 row-tiles x 4 col-groups), warp tile 32x64. Epilogue scatters
// into attention fragment layouts via SMEM, then coalesced copy-out.
// ---------------------------------------------------------------------------
#define PROJ_SMEM ((16384 + 4096) * 4)

__global__ __launch_bounds__(256, 2) void proj_kernel(
    const float* __restrict__ xq, const float* __restrict__ xkv) {
  extern __shared__ float sm[];
  float* Ws = sm;          // [kk8][nfg32][lane][2]; reused as out-frag buffer
  float* Xs = sm + 16384;  // [rt4][kk8][lane][4]

  const int tid = threadIdx.x;
  const int z = blockIdx.z;
  const int row0 = blockIdx.x * 64;
  const float* x = (z == 0) ? xq : xkv;

  {
    const float4* wg = (const float4*)(g_Wf + z * 16384);
    float4* ws4 = (float4*)Ws;
#pragma unroll
    for (int i = tid; i < 4096; i += 256) ws4[i] = wg[i];
#pragma unroll
    for (int i = tid; i < 1024; i += 256) {
      int row = i >> 4, k0 = (i & 15) * 4;
      float4 v = *(const float4*)(x + (size_t)(row0 + row) * 64 + k0);
      int rt = row >> 4, rr = row & 15;
      int r4s = rr & 7, eR = rr >> 3;
      int kk = k0 >> 3, half = (k0 >> 2) & 1;
      float* base = Xs + ((rt * 8 + kk) * 32 + r4s * 4) * 4 + eR + 2 * half;
      base[0] = f2tf(v.x); base[4] = f2tf(v.y);
      base[8] = f2tf(v.z); base[12] = f2tf(v.w);
    }
  }
  __syncthreads();

  const int wid = tid >> 5, lane = tid & 31;
  const int r4 = lane >> 2, c4 = lane & 3;
  const int rt0 = (wid >> 2) * 2;      // warp rows = rt0*16 .. +32
  const int nfg0 = (wid & 3) * 8;      // warp cols = nfg0*8 .. +64

  float4 acc[2][8];
#pragma unroll
  for (int i = 0; i < 2; i++)
#pragma unroll
    for (int j = 0; j < 8; j++) acc[i][j] = make_float4(0.f, 0.f, 0.f, 0.f);

#pragma unroll
  for (int kk = 0; kk < 8; kk++) {
    float4 A0 = *(float4*)(Xs + ((rt0 * 8 + kk) * 32 + lane) * 4);
    float4 A1 = *(float4*)(Xs + (((rt0 + 1) * 8 + kk) * 32 + lane) * 4);
#pragma unroll
    for (int nf = 0; nf < 8; nf++) {
      float2 B = *(float2*)(Ws + ((kk * 32 + nfg0 + nf) * 32 + lane) * 2);
      mma8(acc[0][nf], A0.x, A0.y, A0.z, A0.w, B.x, B.y);
      mma8(acc[1][nf], A1.x, A1.y, A1.z, A1.w, B.x, B.y);
    }
  }
  __syncthreads();  // done with Ws; reuse as out-frag staging

  // Scatter C frags into per-h fragment chunks ([h][2048]) in SMEM.
#pragma unroll
  for (int mt = 0; mt < 2; mt++) {
#pragma unroll
    for (int nf = 0; nf < 8; nf++) {
      float vals[4] = {acc[mt][nf].x, acc[mt][nf].y, acc[mt][nf].z, acc[mt][nf].w};
#pragma unroll
      for (int e2 = 0; e2 < 4; e2++) {
        int eR = e2 >> 1, j = e2 & 1;
        int c = (nfg0 + nf) * 8 + 2 * c4 + j;
        int hh = c >> 5, d = c & 31;
        int qloc = (rt0 + mt) * 16 + r4 + 8 * eR;
        int idx;
        if (z == 0) {
          // Qf: [qt][dd][lane][4], e = eR + 2*eC
          idx = hh * 2048 +
                (((rt0 + mt) * 4 + (d >> 3)) * 32 + r4 * 4 + (d & 3)) * 4 +
                eR + 2 * ((d >> 2) & 1);
        } else if (z == 1) {
          // Kf: [kt][dd][lane][2], p over d+4
          int ktl = qloc >> 3;
          idx = hh * 2048 +
                ((ktl * 4 + (d >> 3)) * 32 + r4 * 4 + (d & 3)) * 2 +
                ((d >> 2) & 1);
        } else {
          // Vf: [kc][nf'][lane][2], p over kv+4; lane=(d&7)*4+(kv&3)
          int kcl = qloc >> 3;
          int rem = qloc & 7;  // == r4
          idx = hh * 2048 +
                ((kcl * 4 + (d >> 3)) * 32 + (d & 7) * 4 + (rem & 3)) * 2 +
                (rem >> 2);
        }
        Ws[idx] = f2tf(vals[e2]);
      }
    }
  }
  __syncthreads();

  // Coalesced copy-out: 8 h-chunks of 2048 floats each.
  const int s = row0 >> 8;
  float* outg = (z == 0) ? g_Qf : (z == 1) ? g_Kf : g_Vf;
  const int sub = (z == 0) ? ((row0 & 255) >> 4) * 128    // float4 units
                           : ((row0 & 255) >> 3) * 64;
  const float4* src = (const float4*)Ws;
  float4* dst = (float4*)outg;
#pragma unroll
  for (int i = tid; i < 4096; i += 256) {
    int hh = i >> 9, wi = i & 511;
    dst[(size_t)(s * 8 + hh) * 2048 + sub + wi] = src[i];
  }
}

// ---------------------------------------------------------------------------
// Fused attention, one block per (s,h). Q frags preloaded to regs via
// coalesced LDG.128; K/V staged as fragment layouts (LDS.64, conflict-free).
// ---------------------------------------------------------------------------
#define ATTN_SMEM ((8192 + 8192 + 256) * 4)

__global__ __launch_bounds__(256, 2) void attn_kernel(
    const float* __restrict__ mask, const float* __restrict__ bias) {
  extern __shared__ float sm[];
  float* Ks = sm;           // [kt][dd][lane][2]
  float* Vs = sm + 8192;    // [kc][nf][lane][2]
  float* ms = sm + 16384;   // [256]

  const int tid = threadIdx.x;
  const int s = blockIdx.x, h = blockIdx.y;
  const size_t chunk = (size_t)(s * 8 + h) * 8192;

  {
    const float4* kg = (const float4*)(g_Kf + chunk);
    const float4* vg = (const float4*)(g_Vf + chunk);
    float4* ks4 = (float4*)Ks;
    float4* vs4 = (float4*)Vs;
#pragma unroll
    for (int i = tid; i < 2048; i += 256) { ks4[i] = kg[i]; vs4[i] = vg[i]; }
    ms[tid] = (mask[s * KV_LEN + tid] - 1.0f) * 1.0e9f;
  }

  const int w = tid >> 5, lane = tid & 31;
  const int r4 = lane >> 2, c4 = lane & 3;
  const int qb[2] = {w * 32, w * 32 + 16};

  // Preload Q A-frags (coalesced LDG.128, lane-major layout)
  float4 qa[2][4];
#pragma unroll
  for (int mt = 0; mt < 2; mt++) {
    const float4* qg = (const float4*)(g_Qf + chunk + (size_t)(w * 2 + mt) * 512);
#pragma unroll
    for (int dd = 0; dd < 4; dd++) qa[mt][dd] = qg[dd * 32 + lane];
  }
  __syncthreads();

  float4 o[2][4];
#pragma unroll
  for (int mt = 0; mt < 2; mt++)
#pragma unroll
    for (int nf = 0; nf < 4; nf++) o[mt][nf] = make_float4(0.f, 0.f, 0.f, 0.f);
  float2 lp[2] = {make_float2(0.f, 0.f), make_float2(0.f, 0.f)};

  const float* Bh = bias + (size_t)h * Q_LEN * KV_LEN;
  const float* bb0[2]; const float* bb1[2];
#pragma unroll
  for (int mt = 0; mt < 2; mt++) {
    bb0[mt] = Bh + (size_t)(qb[mt] + r4) * KV_LEN + 2 * c4;
    bb1[mt] = Bh + (size_t)(qb[mt] + r4 + 8) * KV_LEN + 2 * c4;
  }
  float2 bp[2][2];
#pragma unroll
  for (int mt = 0; mt < 2; mt++) {
    bp[mt][0] = *(const float2*)(bb0[mt]);
    bp[mt][1] = *(const float2*)(bb1[mt]);
  }

  const int src0 = (lane & ~3) | (c4 >> 1);
  const int src2 = src0 + 2;
  const bool odd = (c4 & 1);

#pragma unroll 1
  for (int kv0 = 0; kv0 < KV_LEN; kv0 += 8) {
    const int kt = kv0 >> 3;

    float4 S[2] = {make_float4(0.f, 0.f, 0.f, 0.f), make_float4(0.f, 0.f, 0.f, 0.f)};
#pragma unroll
    for (int dd = 0; dd < 4; dd++) {
      float2 kp = *(float2*)(Ks + ((kt * 4 + dd) * 32 + lane) * 2);
      mma8(S[0], qa[0][dd].x, qa[0][dd].y, qa[0][dd].z, qa[0][dd].w, kp.x, kp.y);
      mma8(S[1], qa[1][dd].x, qa[1][dd].y, qa[1][dd].z, qa[1][dd].w, kp.x, kp.y);
    }

    float2 vp[4];
#pragma unroll
    for (int nf = 0; nf < 4; nf++)
      vp[nf] = *(float2*)(Vs + ((kt * 4 + nf) * 32 + lane) * 2);

    float m0 = ms[kv0 + 2 * c4];
    float m1 = ms[kv0 + 2 * c4 + 1];

    float2 nb[2][2];
    if (kv0 < KV_LEN - 8) {
#pragma unroll
      for (int mt = 0; mt < 2; mt++) {
        nb[mt][0] = *(const float2*)(bb0[mt] + kv0 + 8);
        nb[mt][1] = *(const float2*)(bb1[mt] + kv0 + 8);
      }
    }

#pragma unroll
    for (int mt = 0; mt < 2; mt++) {
      float p0 = __expf(S[mt].x + bp[mt][0].x + m0);
      float p1 = __expf(S[mt].y + bp[mt][0].y + m1);
      float p2 = __expf(S[mt].z + bp[mt][1].x + m0);
      float p3 = __expf(S[mt].w + bp[mt][1].y + m1);
      lp[mt].x += p0 + p1;
      lp[mt].y += p2 + p3;

      float t00 = __shfl_sync(0xffffffffu, p0, src0);
      float t01 = __shfl_sync(0xffffffffu, p1, src0);
      float t20 = __shfl_sync(0xffffffffu, p2, src0);
      float t21 = __shfl_sync(0xffffffffu, p3, src0);
      float u00 = __shfl_sync(0xffffffffu, p0, src2);
      float u01 = __shfl_sync(0xffffffffu, p1, src2);
      float u20 = __shfl_sync(0xffffffffu, p2, src2);
      float u21 = __shfl_sync(0xffffffffu, p3, src2);
      float a0 = odd ? t01 : t00;
      float a1 = odd ? t21 : t20;
      float a2 = odd ? u01 : u00;
      float a3 = odd ? u21 : u20;

#pragma unroll
      for (int nf = 0; nf < 4; nf++)
        mma8(o[mt][nf], a0, a1, a2, a3, vp[nf].x, vp[nf].y);
    }

    if (kv0 < KV_LEN - 8) {
#pragma unroll
      for (int mt = 0; mt < 2; mt++) { bp[mt][0] = nb[mt][0]; bp[mt][1] = nb[mt][1]; }
    }
  }

  // finalize: quad row-sums, normalize, tf32-round, store row-major g_O
#pragma unroll
  for (int mt = 0; mt < 2; mt++) {
    lp[mt].x += __shfl_xor_sync(0xffffffffu, lp[mt].x, 1);
    lp[mt].x += __shfl_xor_sync(0xffffffffu, lp[mt].x, 2);
    lp[mt].y += __shfl_xor_sync(0xffffffffu, lp[mt].y, 1);
    lp[mt].y += __shfl_xor_sync(0xffffffffu, lp[mt].y, 2);
    float inv0 = 1.0f / lp[mt].x;
    float inv8 = 1.0f / lp[mt].y;
    float* base = g_O + ((size_t)s * Q_LEN + qb[mt] + r4) * HD + h * DH;
#pragma unroll
    for (int nf = 0; nf < 4; nf++) {
      int col = nf * 8 + 2 * c4;
      *(float2*)(base + col) =
          make_float2(f2tf(o[mt][nf].x * inv0), f2tf(o[mt][nf].y * inv0));
      *(float2*)(base + 8 * HD + col) =
          make_float2(f2tf(o[mt][nf].z * inv8), f2tf(o[mt][nf].w * inv8));
    }
  }
}

// ---------------------------------------------------------------------------
// Output projection: g_O[32768,256] @ wo[256,64] + bo. Block 128 rows x 64
// cols, warp tile 32x32, K chunked by 64 into frag-layout SMEM (copy-only).
// ---------------------------------------------------------------------------
#define OPROJ_SMEM ((16384 + 8192) * 4)

__global__ __launch_bounds__(256, 2) void oproj_kernel(
    const float* __restrict__ bo, float* __restrict__ out) {
  extern __shared__ float sm[];
  float* Ws = sm;          // Wof frags [kk32][nfg8][lane][2]
  float* Xs = sm + 16384;  // [rt8][kk8][lane][4]

  const int tid = threadIdx.x;
  const int row0 = blockIdx.x * 128;

  {
    const float4* wg = (const float4*)g_Wof;
    float4* ws4 = (float4*)Ws;
#pragma unroll
    for (int i = tid; i < 4096; i += 256) ws4[i] = wg[i];
  }

  const int wid = tid >> 5, lane = tid & 31;
  const int r4 = lane >> 2, c4 = lane & 3;
  const int rt0 = (wid >> 1) * 2;
  const int nfg0 = (wid & 1) * 4;

  float4 acc[2][4];
#pragma unroll
  for (int i = 0; i < 2; i++)
#pragma unroll
    for (int j = 0; j < 4; j++) acc[i][j] = make_float4(0.f, 0.f, 0.f, 0.f);

#pragma unroll 1
  for (int kc = 0; kc < 4; kc++) {
    __syncthreads();
#pragma unroll
    for (int i = tid; i < 2048; i += 256) {
      int row = i >> 4, k0 = (i & 15) * 4;
      float4 v = *(const float4*)(g_O + (size_t)(row0 + row) * 256 + kc * 64 + k0);
      int rt = row >> 4, rr = row & 15;
      int rr4 = rr & 7, eR = rr >> 3;
      int kk = k0 >> 3, half = (k0 >> 2) & 1;
      float* base = Xs + ((rt * 8 + kk) * 32 + rr4 * 4) * 4 + eR + 2 * half;
      base[0] = v.x; base[4] = v.y; base[8] = v.z; base[12] = v.w;
    }
    __syncthreads();

#pragma unroll
    for (int kk = 0; kk < 8; kk++) {
      float4 A0 = *(float4*)(Xs + ((rt0 * 8 + kk) * 32 + lane) * 4);
      float4 A1 = *(float4*)(Xs + (((rt0 + 1) * 8 + kk) * 32 + lane) * 4);
      int kkg = kc * 8 + kk;
#pragma unroll
      for (int nf = 0; nf < 4; nf++) {
        float2 B = *(float2*)(Ws + ((kkg * 8 + nfg0 + nf) * 32 + lane) * 2);
        mma8(acc[0][nf], A0.x, A0.y, A0.z, A0.w, B.x, B.y);
        mma8(acc[1][nf], A1.x, A1.y, A1.z, A1.w, B.x, B.y);
      }
    }
  }

#pragma unroll
  for (int mt = 0; mt < 2; mt++) {
    int row = row0 + (rt0 + mt) * 16 + r4;
#pragma unroll
    for (int nf = 0; nf < 4; nf++) {
      int col = (nfg0 + nf) * 8 + 2 * c4;
      float2 bb = *(const float2*)(bo + col);
      *(float2*)(out + (size_t)row * 64 + col) =
          make_float2(acc[mt][nf].x + bb.x, acc[mt][nf].y + bb.y);
      *(float2*)(out + (size_t)(row + 8) * 64 + col) =
          make_float2(acc[mt][nf].z + bb.x, acc[mt][nf].w + bb.y);
    }
  }
}

// ---------------------------------------------------------------------------
extern "C" void kernel_launch(void* const* d_in, const int* in_sizes, int n_in,
                              void* d_out, int out_size) {
  const float* input_q  = (const float*)d_in[0];
  const float* input_kv = (const float*)d_in[1];
  const float* mask     = (const float*)d_in[2];
  const float* bias     = (const float*)d_in[3];
  const float* wq       = (const float*)d_in[4];
  const float* wk       = (const float*)d_in[5];
  const float* wv       = (const float*)d_in[6];
  const float* wo       = (const float*)d_in[7];
  const float* bo       = (const float*)d_in[8];
  float* out = (float*)d_out;

  cudaFuncSetAttribute(proj_kernel,  cudaFuncAttributeMaxDynamicSharedMemorySize, PROJ_SMEM);
  cudaFuncSetAttribute(attn_kernel,  cudaFuncAttributeMaxDynamicSharedMemorySize, ATTN_SMEM);
  cudaFuncSetAttribute(oproj_kernel, cudaFuncAttributeMaxDynamicSharedMemorySize, OPROJ_SMEM);

  prep_kernel<<<64, 256>>>(wq, wk, wv, wo);
  proj_kernel<<<dim3(ROWS / 64, 1, 3), 256, PROJ_SMEM>>>(input_q, input_kv);
  attn_kernel<<<dim3(S_LEN, NH), 256, ATTN_SMEM>>>(mask, bias);
  oproj_kernel<<<ROWS / 128, 256, OPROJ_SMEM>>>(bo, out);
}

// round 5
// speedup vs baseline: 3.0580x; 1.1887x over previous
#include <cuda_runtime.h>

#define S_LEN 128
#define NH 8
#define INF9 1.0e9f

// Weight fragments, prepped once per launch.
__device__ float g_Wf[3 * 8 * 2048];   // [z][h][kk8][nf4][lane32][2]
__device__ float g_Wof[8 * 2048];      // [h][kk4][nf8][lane32][2]

__device__ __forceinline__ float f2tf(float x) {
  unsigned r;
  asm("cvt.rna.tf32.f32 %0, %1;" : "=r"(r) : "f"(x));
  return __uint_as_float(r);
}

__device__ __forceinline__ void mma8(float4& c, float a0, float a1, float a2,
                                     float a3, float b0, float b1) {
  asm volatile(
      "mma.sync.aligned.m16n8k8.row.col.f32.tf32.tf32.f32 "
      "{%0,%1,%2,%3}, {%4,%5,%6,%7}, {%8,%9}, {%0,%1,%2,%3};"
      : "+f"(c.x), "+f"(c.y), "+f"(c.z), "+f"(c.w)
      : "r"(__float_as_uint(a0)), "r"(__float_as_uint(a1)),
        "r"(__float_as_uint(a2)), "r"(__float_as_uint(a3)),
        "r"(__float_as_uint(b0)), "r"(__float_as_uint(b1)));
}

// ---------------------------------------------------------------------------
// Prep: weights -> per-head lane-major B-fragment layouts (tf32, q pre-scaled)
// ---------------------------------------------------------------------------
__global__ void prep_kernel(const float* __restrict__ wq,
                            const float* __restrict__ wk,
                            const float* __restrict__ wv,
                            const float* __restrict__ wo) {
  const float scale = 0.17677669529663687f;  // 1/sqrt(32)
  for (int id = blockIdx.x * 256 + threadIdx.x; id < 65536; id += 64 * 256) {
    if (id < 49152) {
      int z = id / 16384, id2 = id % 16384;
      int p = id2 & 1, lane = (id2 >> 1) & 31, nf = (id2 >> 6) & 3,
          kk = (id2 >> 8) & 7, h = id2 >> 11;
      int r4 = lane >> 2, c4 = lane & 3;
      const float* w = (z == 0) ? wq : (z == 1) ? wk : wv;
      float v = w[(kk * 8 + c4 + 4 * p) * 256 + h * 32 + nf * 8 + r4];
      if (z == 0) v *= scale;
      g_Wf[id] = f2tf(v);
    } else {
      int id2 = id - 49152;
      int p = id2 & 1, lane = (id2 >> 1) & 31, nf = (id2 >> 6) & 7,
          kk = (id2 >> 9) & 3, h = id2 >> 11;
      int r4 = lane >> 2, c4 = lane & 3;
      g_Wof[id2] = f2tf(wo[(h * 32 + kk * 8 + c4 + 4 * p) * 64 + nf * 8 + r4]);
    }
  }
}

// ---------------------------------------------------------------------------
// Mega-fused kernel: one block per s. 8 warps, warp w owns rows w*32..w*32+31
// (both q and kv). All intermediates in SMEM/regs; out accum in regs.
// ---------------------------------------------------------------------------
#define FUSED_SMEM (57600 * 4)

__global__ __launch_bounds__(256, 1) void fused_kernel(
    const float* __restrict__ xq, const float* __restrict__ xkv,
    const float* __restrict__ mask, const float* __restrict__ bias,
    const float* __restrict__ bo, float* __restrict__ outg) {
  extern __shared__ float sm[];
  float* Xq  = sm;            // [rt16][kk8][lane][4]  A-frags of input_q
  float* Xk  = sm + 16384;    // same for input_kv
  float* Wsm = sm + 32768;    // Wq|Wk|Wv|Wo frags (4 x 2048)
  float* Ks  = sm + 40960;    // [kt32][dd4][lane][2]
  float* Vs  = sm + 49152;    // [kc32][nf4][lane][2]
  float* ms  = sm + 57344;    // [256]

  const int tid = threadIdx.x;
  const int s = blockIdx.x;

  // Stage Xq, Xkv into A-frag layout (tf32)
  for (int i = tid; i < 4096; i += 256) {
    int row = i >> 4, k0 = (i & 15) * 4;
    float4 a = *(const float4*)(xq + (size_t)(s * 256 + row) * 64 + k0);
    float4 b = *(const float4*)(xkv + (size_t)(s * 256 + row) * 64 + k0);
    int rt = row >> 4, rr = row & 15;
    int r4s = rr & 7, eR = rr >> 3;
    int kk = k0 >> 3, half = (k0 >> 2) & 1;
    int off = ((rt * 8 + kk) * 32 + r4s * 4) * 4 + eR + 2 * half;
    Xq[off] = f2tf(a.x); Xq[off + 4] = f2tf(a.y);
    Xq[off + 8] = f2tf(a.z); Xq[off + 12] = f2tf(a.w);
    Xk[off] = f2tf(b.x); Xk[off + 4] = f2tf(b.y);
    Xk[off + 8] = f2tf(b.z); Xk[off + 12] = f2tf(b.w);
  }
  ms[tid] = (mask[s * 256 + tid] - 1.0f) * INF9;

  const int w = tid >> 5, lane = tid & 31;
  const int r4 = lane >> 2, c4 = lane & 3;
  const int rt0 = w * 2;
  const int src0 = (lane & ~3) | (c4 >> 1);
  const int src2 = src0 + 2;
  const bool odd = (c4 & 1);

  float4 oacc[2][8];  // final output accum: rows w*32+mt*16+{r4,r4+8}, 64 cols
#pragma unroll
  for (int i = 0; i < 2; i++)
#pragma unroll
    for (int j = 0; j < 8; j++) oacc[i][j] = make_float4(0.f, 0.f, 0.f, 0.f);

#pragma unroll 1
  for (int h = 0; h < NH; h++) {
    __syncthreads();  // prior head's SMEM reads done (also orders X staging)
    // Stage this head's weight frags (coalesced float4 copies)
    for (int i = tid; i < 2048; i += 256) {
      int z = i >> 9, wi = i & 511;
      float4 v = (z < 3) ? ((const float4*)g_Wf)[(z * 8 + h) * 512 + wi]
                         : ((const float4*)g_Wof)[h * 512 + wi];
      ((float4*)Wsm)[i] = v;
    }
    __syncthreads();

    // ---- Q = Xq @ Wq_h -> qa A-frags (regs only) ----
    float4 qa[2][4];
    {
      float4 acc[2][4];
#pragma unroll
      for (int i = 0; i < 2; i++)
#pragma unroll
        for (int j = 0; j < 4; j++) acc[i][j] = make_float4(0.f, 0.f, 0.f, 0.f);
#pragma unroll
      for (int kk = 0; kk < 8; kk++) {
        float4 A0 = *(float4*)(Xq + ((rt0 * 8 + kk) * 32 + lane) * 4);
        float4 A1 = *(float4*)(Xq + (((rt0 + 1) * 8 + kk) * 32 + lane) * 4);
#pragma unroll
        for (int nf = 0; nf < 4; nf++) {
          float2 B = *(float2*)(Wsm + ((kk * 4 + nf) * 32 + lane) * 2);
          mma8(acc[0][nf], A0.x, A0.y, A0.z, A0.w, B.x, B.y);
          mma8(acc[1][nf], A1.x, A1.y, A1.z, A1.w, B.x, B.y);
        }
      }
#pragma unroll
      for (int mt = 0; mt < 2; mt++)
#pragma unroll
        for (int dd = 0; dd < 4; dd++) {
          float p0 = f2tf(acc[mt][dd].x), p1 = f2tf(acc[mt][dd].y);
          float p2 = f2tf(acc[mt][dd].z), p3 = f2tf(acc[mt][dd].w);
          float t00 = __shfl_sync(0xffffffffu, p0, src0);
          float t01 = __shfl_sync(0xffffffffu, p1, src0);
          float t20 = __shfl_sync(0xffffffffu, p2, src0);
          float t21 = __shfl_sync(0xffffffffu, p3, src0);
          float u00 = __shfl_sync(0xffffffffu, p0, src2);
          float u01 = __shfl_sync(0xffffffffu, p1, src2);
          float u20 = __shfl_sync(0xffffffffu, p2, src2);
          float u21 = __shfl_sync(0xffffffffu, p3, src2);
          qa[mt][dd] = make_float4(odd ? t01 : t00, odd ? t21 : t20,
                                   odd ? u01 : u00, odd ? u21 : u20);
        }
    }

    // ---- K = Xkv @ Wk_h -> Ks scatter ----
    {
      float4 acc[2][4];
#pragma unroll
      for (int i = 0; i < 2; i++)
#pragma unroll
        for (int j = 0; j < 4; j++) acc[i][j] = make_float4(0.f, 0.f, 0.f, 0.f);
#pragma unroll
      for (int kk = 0; kk < 8; kk++) {
        float4 A0 = *(float4*)(Xk + ((rt0 * 8 + kk) * 32 + lane) * 4);
        float4 A1 = *(float4*)(Xk + (((rt0 + 1) * 8 + kk) * 32 + lane) * 4);
#pragma unroll
        for (int nf = 0; nf < 4; nf++) {
          float2 B = *(float2*)(Wsm + 2048 + ((kk * 4 + nf) * 32 + lane) * 2);
          mma8(acc[0][nf], A0.x, A0.y, A0.z, A0.w, B.x, B.y);
          mma8(acc[1][nf], A1.x, A1.y, A1.z, A1.w, B.x, B.y);
        }
      }
#pragma unroll
      for (int mt = 0; mt < 2; mt++)
#pragma unroll
        for (int nf = 0; nf < 4; nf++) {
          float vals[4] = {f2tf(acc[mt][nf].x), f2tf(acc[mt][nf].y),
                           f2tf(acc[mt][nf].z), f2tf(acc[mt][nf].w)};
#pragma unroll
          for (int e2 = 0; e2 < 4; e2++) {
            int eR = e2 >> 1, j = e2 & 1;
            int kvrow = w * 32 + mt * 16 + r4 + 8 * eR;
            int dim = nf * 8 + 2 * c4 + j;
            int idx = (((kvrow >> 3) * 4 + nf) * 32 + r4 * 4 + (dim & 3)) * 2 +
                      ((dim >> 2) & 1);
            Ks[idx] = vals[e2];
          }
        }
    }

    // ---- V = Xkv @ Wv_h -> Vs scatter ----
    {
      float4 acc[2][4];
#pragma unroll
      for (int i = 0; i < 2; i++)
#pragma unroll
        for (int j = 0; j < 4; j++) acc[i][j] = make_float4(0.f, 0.f, 0.f, 0.f);
#pragma unroll
      for (int kk = 0; kk < 8; kk++) {
        float4 A0 = *(float4*)(Xk + ((rt0 * 8 + kk) * 32 + lane) * 4);
        float4 A1 = *(float4*)(Xk + (((rt0 + 1) * 8 + kk) * 32 + lane) * 4);
#pragma unroll
        for (int nf = 0; nf < 4; nf++) {
          float2 B = *(float2*)(Wsm + 4096 + ((kk * 4 + nf) * 32 + lane) * 2);
          mma8(acc[0][nf], A0.x, A0.y, A0.z, A0.w, B.x, B.y);
          mma8(acc[1][nf], A1.x, A1.y, A1.z, A1.w, B.x, B.y);
        }
      }
#pragma unroll
      for (int mt = 0; mt < 2; mt++)
#pragma unroll
        for (int nf = 0; nf < 4; nf++) {
          float vals[4] = {f2tf(acc[mt][nf].x), f2tf(acc[mt][nf].y),
                           f2tf(acc[mt][nf].z), f2tf(acc[mt][nf].w)};
#pragma unroll
          for (int e2 = 0; e2 < 4; e2++) {
            int eR = e2 >> 1, j = e2 & 1;
            int kvrow = w * 32 + mt * 16 + r4 + 8 * eR;
            int dim = nf * 8 + 2 * c4 + j;
            int idx = (((kvrow >> 3) * 4 + (dim >> 3)) * 32 + (dim & 7) * 4 +
                       (kvrow & 3)) * 2 + ((kvrow >> 2) & 1);
            Vs[idx] = vals[e2];
          }
        }
    }
    __syncthreads();  // K/V tiles ready

    // ---- attention over this head ----
    float4 o[2][4];
#pragma unroll
    for (int mt = 0; mt < 2; mt++)
#pragma unroll
      for (int nf = 0; nf < 4; nf++) o[mt][nf] = make_float4(0.f, 0.f, 0.f, 0.f);
    float2 lp[2] = {make_float2(0.f, 0.f), make_float2(0.f, 0.f)};

    const float* Bh = bias + (size_t)h * 65536;
    const float* bb0[2]; const float* bb1[2];
#pragma unroll
    for (int mt = 0; mt < 2; mt++) {
      bb0[mt] = Bh + (size_t)(w * 32 + mt * 16 + r4) * 256 + 2 * c4;
      bb1[mt] = Bh + (size_t)(w * 32 + mt * 16 + r4 + 8) * 256 + 2 * c4;
    }
    float2 bp[2][2];
#pragma unroll
    for (int mt = 0; mt < 2; mt++) {
      bp[mt][0] = *(const float2*)(bb0[mt]);
      bp[mt][1] = *(const float2*)(bb1[mt]);
    }

#pragma unroll 1
    for (int kv0 = 0; kv0 < 256; kv0 += 8) {
      const int kt = kv0 >> 3;

      float4 S[2] = {make_float4(0.f, 0.f, 0.f, 0.f),
                     make_float4(0.f, 0.f, 0.f, 0.f)};
#pragma unroll
      for (int dd = 0; dd < 4; dd++) {
        float2 kp = *(float2*)(Ks + ((kt * 4 + dd) * 32 + lane) * 2);
        mma8(S[0], qa[0][dd].x, qa[0][dd].y, qa[0][dd].z, qa[0][dd].w, kp.x, kp.y);
        mma8(S[1], qa[1][dd].x, qa[1][dd].y, qa[1][dd].z, qa[1][dd].w, kp.x, kp.y);
      }

      float2 vp[4];
#pragma unroll
      for (int nf = 0; nf < 4; nf++)
        vp[nf] = *(float2*)(Vs + ((kt * 4 + nf) * 32 + lane) * 2);

      float m0 = ms[kv0 + 2 * c4];
      float m1 = ms[kv0 + 2 * c4 + 1];

      float2 nb[2][2];
      if (kv0 < 248) {
#pragma unroll
        for (int mt = 0; mt < 2; mt++) {
          nb[mt][0] = *(const float2*)(bb0[mt] + kv0 + 8);
          nb[mt][1] = *(const float2*)(bb1[mt] + kv0 + 8);
        }
      }

#pragma unroll
      for (int mt = 0; mt < 2; mt++) {
        float p0 = __expf(S[mt].x + bp[mt][0].x + m0);
        float p1 = __expf(S[mt].y + bp[mt][0].y + m1);
        float p2 = __expf(S[mt].z + bp[mt][1].x + m0);
        float p3 = __expf(S[mt].w + bp[mt][1].y + m1);
        lp[mt].x += p0 + p1;
        lp[mt].y += p2 + p3;

        float t00 = __shfl_sync(0xffffffffu, p0, src0);
        float t01 = __shfl_sync(0xffffffffu, p1, src0);
        float t20 = __shfl_sync(0xffffffffu, p2, src0);
        float t21 = __shfl_sync(0xffffffffu, p3, src0);
        float u00 = __shfl_sync(0xffffffffu, p0, src2);
        float u01 = __shfl_sync(0xffffffffu, p1, src2);
        float u20 = __shfl_sync(0xffffffffu, p2, src2);
        float u21 = __shfl_sync(0xffffffffu, p3, src2);
        float a0 = odd ? t01 : t00;
        float a1 = odd ? t21 : t20;
        float a2 = odd ? u01 : u00;
        float a3 = odd ? u21 : u20;

#pragma unroll
        for (int nf = 0; nf < 4; nf++)
          mma8(o[mt][nf], a0, a1, a2, a3, vp[nf].x, vp[nf].y);
      }

      if (kv0 < 248) {
#pragma unroll
        for (int mt = 0; mt < 2; mt++) {
          bp[mt][0] = nb[mt][0];
          bp[mt][1] = nb[mt][1];
        }
      }
    }

    // ---- normalize O, convert to A-frags, out += O @ Wo_h ----
#pragma unroll
    for (int mt = 0; mt < 2; mt++) {
      lp[mt].x += __shfl_xor_sync(0xffffffffu, lp[mt].x, 1);
      lp[mt].x += __shfl_xor_sync(0xffffffffu, lp[mt].x, 2);
      lp[mt].y += __shfl_xor_sync(0xffffffffu, lp[mt].y, 1);
      lp[mt].y += __shfl_xor_sync(0xffffffffu, lp[mt].y, 2);
      float inv0 = 1.0f / lp[mt].x;
      float inv8 = 1.0f / lp[mt].y;
#pragma unroll
      for (int kk = 0; kk < 4; kk++) {
        float p0 = f2tf(o[mt][kk].x * inv0), p1 = f2tf(o[mt][kk].y * inv0);
        float p2 = f2tf(o[mt][kk].z * inv8), p3 = f2tf(o[mt][kk].w * inv8);
        float t00 = __shfl_sync(0xffffffffu, p0, src0);
        float t01 = __shfl_sync(0xffffffffu, p1, src0);
        float t20 = __shfl_sync(0xffffffffu, p2, src0);
        float t21 = __shfl_sync(0xffffffffu, p3, src0);
        float u00 = __shfl_sync(0xffffffffu, p0, src2);
        float u01 = __shfl_sync(0xffffffffu, p1, src2);
        float u20 = __shfl_sync(0xffffffffu, p2, src2);
        float u21 = __shfl_sync(0xffffffffu, p3, src2);
        float a0 = odd ? t01 : t00;
        float a1 = odd ? t21 : t20;
        float a2 = odd ? u01 : u00;
        float a3 = odd ? u21 : u20;
#pragma unroll
        for (int nf = 0; nf < 8; nf++) {
          float2 B = *(float2*)(Wsm + 6144 + ((kk * 8 + nf) * 32 + lane) * 2);
          mma8(oacc[mt][nf], a0, a1, a2, a3, B.x, B.y);
        }
      }
    }
  }

  // ---- epilogue: + bo, store ----
#pragma unroll
  for (int mt = 0; mt < 2; mt++) {
    int row = s * 256 + w * 32 + mt * 16 + r4;
#pragma unroll
    for (int nf = 0; nf < 8; nf++) {
      int col = nf * 8 + 2 * c4;
      float2 bb = *(const float2*)(bo + col);
      *(float2*)(outg + (size_t)row * 64 + col) =
          make_float2(oacc[mt][nf].x + bb.x, oacc[mt][nf].y + bb.y);
      *(float2*)(outg + (size_t)(row + 8) * 64 + col) =
          make_float2(oacc[mt][nf].z + bb.x, oacc[mt][nf].w + bb.y);
    }
  }
}

// ---------------------------------------------------------------------------
extern "C" void kernel_launch(void* const* d_in, const int* in_sizes, int n_in,
                              void* d_out, int out_size) {
  const float* input_q  = (const float*)d_in[0];
  const float* input_kv = (const float*)d_in[1];
  const float* mask     = (const float*)d_in[2];
  const float* bias     = (const float*)d_in[3];
  const float* wq       = (const float*)d_in[4];
  const float* wk       = (const float*)d_in[5];
  const float* wv       = (const float*)d_in[6];
  const float* wo       = (const float*)d_in[7];
  const float* bo       = (const float*)d_in[8];
  float* out = (float*)d_out;

  cudaFuncSetAttribute(fused_kernel, cudaFuncAttributeMaxDynamicSharedMemorySize,
                       FUSED_SMEM);

  prep_kernel<<<64, 256>>>(wq, wk, wv, wo);
  fused_kernel<<<S_LEN, 256, FUSED_SMEM>>>(input_q, input_kv, mask, bias, bo, out);
}